// round 8
// baseline (speedup 1.0000x reference)
#include <cuda_runtime.h>
#include <cstdint>

#define B_ 4
#define N_ 50000
#define E_ 800000
#define C_ 128
#define NOISE_ 100
#define NL_ 5
#define MTOT 200000
#define LAP_G 512
#define GEMM_BLOCKS 1563  /* ceil(200000/128) */

// ---------------- device heap (no allocations allowed) ----------------
#define SZ 25600000L                       // B*N*C floats
#define OFF_LX (3L*SZ)
#define OFF_Z0 (4L*SZ)
#define OFF_Z1 (5L*SZ)
#define OFF_VALS (6L*SZ)                   // sorted vals, B*E
#define OFF_PARTA (OFF_VALS + (long)B_*E_)             // GEMM z-stats partials
#define OFF_PARTB (OFF_PARTA + (long)GEMM_BLOCKS*256)  // lap lx-stats partials
#define OFF_WP (OFF_PARTB + (long)LAP_G*256)
#define OFF_BP (OFF_WP + 256L*C_)
#define HEAP_F (OFF_BP + 128L)

#define OFFI_CNT 0
#define OFFI_RP  (B_*N_)                   // B*(N+1)
#define OFFI_COLS (OFFI_RP + B_*(N_+1))
#define IHEAP (OFFI_COLS + B_*E_)

__device__ __align__(256) float g_heap[HEAP_F];
__device__ __align__(256) int   g_iheap[IHEAP];

// ---------------- helpers ----------------
__device__ __forceinline__ float eluf(float x) {
    return x > 0.f ? x : (__expf(x) - 1.f);
}
__device__ __forceinline__ uint32_t smem_u32(const void* p) {
    uint32_t a;
    asm("{ .reg .u64 t; cvta.to.shared.u64 t, %1; cvt.u32.u64 %0, t; }" : "=r"(a) : "l"(p));
    return a;
}
__device__ __forceinline__ unsigned long long pk2(float x) {
    unsigned long long r; unsigned int u = __float_as_uint(x);
    asm("mov.b64 %0, {%1, %1};" : "=l"(r) : "r"(u));
    return r;
}
__device__ __forceinline__ void fma2(unsigned long long& d, unsigned long long a, unsigned long long b) {
    asm("fma.rn.f32x2 %0, %1, %2, %0;" : "+l"(d) : "l"(a), "l"(b));
}
__device__ __forceinline__ void upk2(unsigned long long v, float& lo, float& hi) {
    unsigned int a, b;
    asm("mov.b64 {%0, %1}, %2;" : "=r"(a), "=r"(b) : "l"(v));
    lo = __uint_as_float(a); hi = __uint_as_float(b);
}
__device__ __forceinline__ void cpa16(uint32_t dst, const void* src, uint32_t bytes) {
    asm volatile("cp.async.cg.shared.global [%0], [%1], 16, %2;"
                 :: "r"(dst), "l"(src), "r"(bytes) : "memory");
}
__device__ __forceinline__ void cpa_commit() {
    asm volatile("cp.async.commit_group;" ::: "memory");
}
template <int N>
__device__ __forceinline__ void cpa_wait() {
    asm volatile("cp.async.wait_group %0;" :: "n"(N) : "memory");
}

// ---------------- CSR build ----------------
__global__ void k_zero_cnt() {
    int i = blockIdx.x * 256 + threadIdx.x;
    if (i < B_ * N_) g_iheap[OFFI_CNT + i] = 0;
}

__global__ void k_hist(const int* __restrict__ rows) {
    int i = blockIdx.x * 256 + threadIdx.x;
    if (i < B_ * E_) {
        int b = i / E_;
        atomicAdd(&g_iheap[OFFI_CNT + b * N_ + rows[i]], 1);
    }
}

__global__ void k_scan() {  // grid = B_, block = 1024
    int b = blockIdx.x;
    int* cnt = g_iheap + OFFI_CNT + b * N_;
    int* rp  = g_iheap + OFFI_RP  + b * (N_ + 1);
    __shared__ int s[1024];
    __shared__ int carry;
    if (threadIdx.x == 0) { carry = 0; rp[0] = 0; }
    __syncthreads();
    for (int base = 0; base < N_; base += 1024) {
        int i = base + threadIdx.x;
        int v = (i < N_) ? cnt[i] : 0;
        s[threadIdx.x] = v;
        __syncthreads();
        for (int off = 1; off < 1024; off <<= 1) {
            int t = (threadIdx.x >= off) ? s[threadIdx.x - off] : 0;
            __syncthreads();
            s[threadIdx.x] += t;
            __syncthreads();
        }
        if (i < N_) { rp[i + 1] = carry + s[threadIdx.x]; cnt[i] = 0; }
        __syncthreads();
        if (threadIdx.x == 1023) carry += s[1023];
        __syncthreads();
    }
}

__global__ void k_scatter(const int* __restrict__ rows, const int* __restrict__ colsIn,
                          const float* __restrict__ valsIn) {
    int i = blockIdx.x * 256 + threadIdx.x;
    if (i >= B_ * E_) return;
    int b = i / E_;
    int r = rows[i];
    int pos = g_iheap[OFFI_RP + b * (N_ + 1) + r] + atomicAdd(&g_iheap[OFFI_CNT + b * N_ + r], 1);
    g_iheap[OFFI_COLS + b * E_ + pos] = colsIn[i];
    g_heap[OFF_VALS + (long)b * E_ + pos] = valsIn[i];
}

// ---------------- input projection small term ----------------
__global__ void k_proj(const float* __restrict__ inp, const float* __restrict__ Win,
                       const float* __restrict__ bin, const float* __restrict__ bno, long ooff) {
    long i = (long)blockIdx.x * 256 + threadIdx.x;
    if (i >= (long)MTOT * C_) return;
    int c = (int)(i & 127);
    long r = i >> 7;
    const float* p = inp + r * 3;
    float v = bin[c] + bno[c] + p[0] * Win[c] + p[1] * Win[C_ + c] + p[2] * Win[2 * C_ + c];
    g_heap[ooff + i] = v;
}

// ---------------- Laplacian gather + fused lx-stats -------------------------
// persistent: grid LAP_G blocks x 256 thr; warp per row, strided. lx -> OFF_LX,
// per-block stats partials -> PARTB[blockIdx].
__global__ void __launch_bounds__(256) k_lap(long zoff) {
    const float* z = g_heap + zoff;
    float* lx = g_heap + OFF_LX;
    int wid = threadIdx.x >> 5;
    int lane = threadIdx.x & 31;
    int c4 = lane * 4;
    float ss0 = 0.f, ss1 = 0.f, ss2 = 0.f, ss3 = 0.f;
    float qq0 = 0.f, qq1 = 0.f, qq2 = 0.f, qq3 = 0.f;

    for (int row = blockIdx.x * 8 + wid; row < MTOT; row += LAP_G * 8) {
        int b = row / N_;
        int rr = row - b * N_;
        const int* rp = g_iheap + OFFI_RP + b * (N_ + 1);
        const int* cols = g_iheap + OFFI_COLS + b * E_;
        const float* vals = g_heap + OFF_VALS + (long)b * E_;
        int e0 = rp[rr], e1 = rp[rr + 1];
        const float* zb = z + (size_t)b * N_ * C_;
        float4 acc = make_float4(0.f, 0.f, 0.f, 0.f);
        for (int e = e0; e < e1; e += 32) {
            int idx = e + lane;
            int cc = 0; float vv = 0.f;
            if (idx < e1) { cc = cols[idx]; vv = vals[idx]; }
            int mE = min(32, e1 - e);
            int t = 0;
            for (; t + 4 <= mE; t += 4) {
                int ci0 = __shfl_sync(0xffffffffu, cc, t);
                int ci1 = __shfl_sync(0xffffffffu, cc, t + 1);
                int ci2 = __shfl_sync(0xffffffffu, cc, t + 2);
                int ci3 = __shfl_sync(0xffffffffu, cc, t + 3);
                float v0 = __shfl_sync(0xffffffffu, vv, t);
                float v1 = __shfl_sync(0xffffffffu, vv, t + 1);
                float v2 = __shfl_sync(0xffffffffu, vv, t + 2);
                float v3 = __shfl_sync(0xffffffffu, vv, t + 3);
                float4 x0 = *reinterpret_cast<const float4*>(&zb[(size_t)ci0 * C_ + c4]);
                float4 x1 = *reinterpret_cast<const float4*>(&zb[(size_t)ci1 * C_ + c4]);
                float4 x2 = *reinterpret_cast<const float4*>(&zb[(size_t)ci2 * C_ + c4]);
                float4 x3 = *reinterpret_cast<const float4*>(&zb[(size_t)ci3 * C_ + c4]);
                acc.x += v0 * x0.x; acc.y += v0 * x0.y; acc.z += v0 * x0.z; acc.w += v0 * x0.w;
                acc.x += v1 * x1.x; acc.y += v1 * x1.y; acc.z += v1 * x1.z; acc.w += v1 * x1.w;
                acc.x += v2 * x2.x; acc.y += v2 * x2.y; acc.z += v2 * x2.z; acc.w += v2 * x2.w;
                acc.x += v3 * x3.x; acc.y += v3 * x3.y; acc.z += v3 * x3.z; acc.w += v3 * x3.w;
            }
            for (; t < mE; ++t) {
                int c = __shfl_sync(0xffffffffu, cc, t);
                float v = __shfl_sync(0xffffffffu, vv, t);
                float4 xv = *reinterpret_cast<const float4*>(&zb[(size_t)c * C_ + c4]);
                acc.x += v * xv.x; acc.y += v * xv.y; acc.z += v * xv.z; acc.w += v * xv.w;
            }
        }
        *reinterpret_cast<float4*>(&lx[(size_t)row * C_ + c4]) = acc;
        ss0 += acc.x; ss1 += acc.y; ss2 += acc.z; ss3 += acc.w;
        qq0 += acc.x * acc.x; qq1 += acc.y * acc.y; qq2 += acc.z * acc.z; qq3 += acc.w * acc.w;
    }

    __shared__ float sm[8 * 256];
    float* row = sm + wid * 256;
    row[c4 + 0] = ss0; row[c4 + 1] = ss1; row[c4 + 2] = ss2; row[c4 + 3] = ss3;
    row[128 + c4 + 0] = qq0; row[128 + c4 + 1] = qq1; row[128 + c4 + 2] = qq2; row[128 + c4 + 3] = qq3;
    __syncthreads();
    float tot = 0.f;
#pragma unroll
    for (int r = 0; r < 8; ++r) tot += sm[r * 256 + threadIdx.x];
    g_heap[OFF_PARTB + (long)blockIdx.x * 256 + threadIdx.x] = tot;
}

// ---------------- fold BN into weights: Wp = s.*W, bp = b + (beta - m*s)@W ----
// stats: k<128 from PARTA (GEMM_BLOCKS partials), k>=128 from PARTB (LAP_G).
__global__ void k_prep(const float* __restrict__ gamma, const float* __restrict__ beta,
                       const float* __restrict__ Wraw, const float* __restrict__ braw, int K) {
    __shared__ float ss[256], tt[256];
    int k = threadIdx.x;
    if (k < K) {
        int c = k & 127;
        float s = 0.f, q = 0.f;
        if (k < 128) {
#pragma unroll 4
            for (int g = 0; g < GEMM_BLOCKS; ++g) {
                s += g_heap[OFF_PARTA + (long)g * 256 + c];
                q += g_heap[OFF_PARTA + (long)g * 256 + 128 + c];
            }
        } else {
#pragma unroll 4
            for (int g = 0; g < LAP_G; ++g) {
                s += g_heap[OFF_PARTB + (long)g * 256 + c];
                q += g_heap[OFF_PARTB + (long)g * 256 + 128 + c];
            }
        }
        float inv = 1.f / (float)MTOT;
        float mean = s * inv;
        float var = q * inv - mean * mean;
        float sc = gamma[k] * rsqrtf(var + 1e-5f);
        ss[k] = sc;
        tt[k] = beta[k] - mean * sc;
    }
    __syncthreads();
    float* Wp = g_heap + OFF_WP;
    for (int idx = threadIdx.x; idx < K * C_; idx += 256) {
        int kk = idx >> 7;
        Wp[idx] = ss[kk] * Wraw[idx];
    }
    if (threadIdx.x < C_) {
        int c = threadIdx.x;
        float acc = braw[c];
        for (int kk = 0; kk < K; ++kk) acc += tt[kk] * Wraw[kk * C_ + c];
        g_heap[OFF_BP + c] = acc;
    }
}

// ---------------- raw weight -> fp32 Wp, zero-padded to Kpad rows -------------
__global__ void k_wconv(const float* __restrict__ W, int K, int Kpad) {
    float* Wp = g_heap + OFF_WP;
    for (int idx = blockIdx.x * 256 + threadIdx.x; idx < Kpad * C_; idx += gridDim.x * 256) {
        int k = idx >> 7;
        Wp[idx] = (k < K) ? W[idx] : 0.f;
    }
}

// ---------------- f32x2 SGEMM, 3-stage cp.async, fused z=elu(out) + z-stats --
// out[M,128] = [A0 | A1] @ Wp + bias (+resid). A tile [128][36] (bank-swizzled
// in 4-col groups), W tile [32][132]. z-stats partials -> PARTA[blockIdx].
#define AS_STRIDE 36
#define WS_STRIDE 132
#define AS_BYTES (128 * AS_STRIDE * 4)   /* 18432 */
#define WS_BYTES (32 * WS_STRIDE * 4)    /* 16896 */
#define BUF_BYTES (AS_BYTES + WS_BYTES)  /* 35328 */
#define SG_SMEM (3 * BUF_BYTES)          /* 105984 */

__global__ void __launch_bounds__(256, 2) k_sgemm(
    const float* __restrict__ Aext, long a0off, int lda0, long a1off,
    long boff, long roff, long ooff, long zoff, int K, int Kpad)
{
    extern __shared__ float smf[];
    const float* A0 = Aext ? Aext : g_heap + a0off;
    const float* A1 = (a1off >= 0) ? g_heap + a1off : (const float*)0;
    const float* Wp = g_heap + OFF_WP;
    const float* bias  = (boff >= 0) ? g_heap + boff : (const float*)0;
    const float* resid = (roff >= 0) ? g_heap + roff : (const float*)0;
    float* out = g_heap + ooff;
    float* zout = (zoff >= 0) ? g_heap + zoff : (float*)0;

    int tid = threadIdx.x;
    int tx = tid & 15, ty = tid >> 4;
    int rowBase = blockIdx.x * 128;
    int c0 = tx * 8;
    int r0 = ty * 8;
    uint32_t sbase = smem_u32(smf);

    auto prefetch = [&](int c) {
        uint32_t asA = sbase + (c % 3) * BUF_BYTES;
        uint32_t wsA = asA + AS_BYTES;
        int kbase = c * 32;
        const float* src; int slda; int ksb;
        if (A1 && kbase >= C_) { src = A1; slda = C_; ksb = kbase - C_; }
        else { src = A0; slda = lda0; ksb = kbase; }
#pragma unroll
        for (int j = 0; j < 4; ++j) {
            int idx = tid + j * 256;          // [m 128][kq 8]
            int m = idx >> 3, kq = idx & 7;
            int grow = rowBase + m;
            int gk = kbase + kq * 4;
            int nb = K - gk; nb = nb < 0 ? 0 : (nb > 4 ? 4 : nb);
            uint32_t bytes = (grow < MTOT) ? (uint32_t)(nb * 4) : 0u;
            int growc = grow < MTOT ? grow : (MTOT - 1);
            const float* s = src + (long)growc * slda + (ksb + kq * 4);
            uint32_t dst = asA + (uint32_t)((m * AS_STRIDE + ((kq * 4) ^ (((m >> 3) & 1) << 2))) * 4);
            cpa16(dst, s, bytes);
        }
#pragma unroll
        for (int j = 0; j < 4; ++j) {
            int idx = tid + j * 256;          // [k 32][cq 32]
            int k = idx >> 5, cq = idx & 31;
            uint32_t dst = wsA + (uint32_t)((k * WS_STRIDE + cq * 4) * 4);
            cpa16(dst, Wp + (long)(kbase + k) * C_ + cq * 4, 16);
        }
        cpa_commit();
    };

    unsigned long long acc[8][4];
#pragma unroll
    for (int i = 0; i < 8; i++)
#pragma unroll
        for (int j = 0; j < 4; j++) acc[i][j] = 0ull;

    int nC = Kpad >> 5;
    prefetch(0);
    if (nC > 1) prefetch(1);
    int sw = (ty & 1) << 2;

    for (int c = 0; c < nC; ++c) {
        if (c + 2 < nC)      { prefetch(c + 2); cpa_wait<2>(); }
        else if (c + 1 < nC) { cpa_wait<1>(); }
        else                 { cpa_wait<0>(); }
        __syncthreads();
        const float* asf = smf + (c % 3) * (BUF_BYTES / 4);
        const float* wsf = asf + (AS_BYTES / 4);
#pragma unroll
        for (int k4 = 0; k4 < 8; ++k4) {
            int kcol = (k4 * 4) ^ sw;
            float4 a4[8];
#pragma unroll
            for (int i = 0; i < 8; ++i)
                a4[i] = *reinterpret_cast<const float4*>(&asf[(r0 + i) * AS_STRIDE + kcol]);
#pragma unroll
            for (int kk = 0; kk < 4; ++kk) {
                const ulonglong2* wp2 = reinterpret_cast<const ulonglong2*>(&wsf[(k4 * 4 + kk) * WS_STRIDE + c0]);
                ulonglong2 w0 = wp2[0], w1 = wp2[1];
#pragma unroll
                for (int i = 0; i < 8; ++i) {
                    float av = (kk == 0) ? a4[i].x : (kk == 1) ? a4[i].y : (kk == 2) ? a4[i].z : a4[i].w;
                    unsigned long long a2 = pk2(av);
                    fma2(acc[i][0], a2, w0.x);
                    fma2(acc[i][1], a2, w0.y);
                    fma2(acc[i][2], a2, w1.x);
                    fma2(acc[i][3], a2, w1.y);
                }
            }
        }
        __syncthreads();
    }

    float bv[8];
#pragma unroll
    for (int j = 0; j < 8; j++) bv[j] = bias ? bias[c0 + j] : 0.f;
    float st_s[8], st_q[8];
#pragma unroll
    for (int j = 0; j < 8; j++) { st_s[j] = 0.f; st_q[j] = 0.f; }

#pragma unroll
    for (int i = 0; i < 8; i++) {
        int grow = rowBase + r0 + i;
        if (grow >= MTOT) continue;
        float o[8];
#pragma unroll
        for (int j = 0; j < 4; j++) {
            float lo, hi;
            upk2(acc[i][j], lo, hi);
            o[2 * j] = lo + bv[2 * j];
            o[2 * j + 1] = hi + bv[2 * j + 1];
        }
        if (resid) {
#pragma unroll
            for (int j = 0; j < 8; j++) o[j] += resid[(long)grow * C_ + c0 + j];
        }
        float4* op = reinterpret_cast<float4*>(&out[(long)grow * C_ + c0]);
        op[0] = make_float4(o[0], o[1], o[2], o[3]);
        op[1] = make_float4(o[4], o[5], o[6], o[7]);
        if (zout) {
            float zv[8];
#pragma unroll
            for (int j = 0; j < 8; j++) {
                zv[j] = eluf(o[j]);
                st_s[j] += zv[j];
                st_q[j] += zv[j] * zv[j];
            }
            float4* zp = reinterpret_cast<float4*>(&zout[(long)grow * C_ + c0]);
            zp[0] = make_float4(zv[0], zv[1], zv[2], zv[3]);
            zp[1] = make_float4(zv[4], zv[5], zv[6], zv[7]);
        }
    }

    if (zout) {   // per-CTA stats partial (deterministic)
        __syncthreads();   // smem buffers no longer needed
#pragma unroll
        for (int j = 0; j < 8; j++) {
            smf[ty * 256 + c0 + j] = st_s[j];
            smf[ty * 256 + 128 + c0 + j] = st_q[j];
        }
        __syncthreads();
        float tot = 0.f;
#pragma unroll
        for (int r = 0; r < 16; ++r) tot += smf[r * 256 + tid];
        g_heap[OFF_PARTA + (long)blockIdx.x * 256 + tid] = tot;
    }
}

// ---------------- final: mu = elu(h)@W_mu + b_mu + inputs; y = logvar --------
__global__ void k_final(long hoff, const float* __restrict__ inp,
                        const float* __restrict__ Wmu, const float* __restrict__ bmu,
                        const float* __restrict__ logv, float* __restrict__ out) {
    int warp = (blockIdx.x * blockDim.x + threadIdx.x) >> 5;
    int lane = threadIdx.x & 31;
    if (warp >= MTOT) return;
    const float* h = g_heap + hoff + (size_t)warp * C_;
    float4 hv = *reinterpret_cast<const float4*>(&h[lane * 4]);
    float e0 = eluf(hv.x), e1 = eluf(hv.y), e2 = eluf(hv.z), e3 = eluf(hv.w);
    int c0 = lane * 4;
    float p0, p1, p2;
    p0 = e0 * Wmu[c0 * 3 + 0] + e1 * Wmu[(c0 + 1) * 3 + 0] + e2 * Wmu[(c0 + 2) * 3 + 0] + e3 * Wmu[(c0 + 3) * 3 + 0];
    p1 = e0 * Wmu[c0 * 3 + 1] + e1 * Wmu[(c0 + 1) * 3 + 1] + e2 * Wmu[(c0 + 2) * 3 + 1] + e3 * Wmu[(c0 + 3) * 3 + 1];
    p2 = e0 * Wmu[c0 * 3 + 2] + e1 * Wmu[(c0 + 1) * 3 + 2] + e2 * Wmu[(c0 + 2) * 3 + 2] + e3 * Wmu[(c0 + 3) * 3 + 2];
#pragma unroll
    for (int off = 16; off; off >>= 1) {
        p0 += __shfl_xor_sync(0xffffffffu, p0, off);
        p1 += __shfl_xor_sync(0xffffffffu, p1, off);
        p2 += __shfl_xor_sync(0xffffffffu, p2, off);
    }
    if (lane < 3) {
        float pv = (lane == 0) ? p0 : ((lane == 1) ? p1 : p2);
        float mu = pv + bmu[lane] + inp[(size_t)warp * 3 + lane];
        out[(size_t)warp * 3 + lane] = mu;
        out[(size_t)MTOT * 3 + (size_t)warp * 3 + lane] = logv[0];
    }
}

// ---------------- host orchestration ----------------
static long off_x(int i) { return (long)i * SZ; }

extern "C" void kernel_launch(void* const* d_in, const int* in_sizes, int n_in,
                              void* d_out, int out_size) {
    const float* inputs = (const float*)d_in[0];
    const float* noise  = (const float*)d_in[1];
    const int*   Lr = (const int*)d_in[3];
    const int*   Lc = (const int*)d_in[4];
    const float* Lv = (const float*)d_in[5];
    const float* W_in = (const float*)d_in[6];
    const float* b_in = (const float*)d_in[7];
    const float* W_no = (const float*)d_in[8];
    const float* b_no = (const float*)d_in[9];
    const float* rng  = (const float*)d_in[10];
    const float* rnb  = (const float*)d_in[11];
    const float* rnW  = (const float*)d_in[12];
    const float* rnbs = (const float*)d_in[13];
    const float* g2   = (const float*)d_in[14];
    const float* be2  = (const float*)d_in[15];
    const float* W2   = (const float*)d_in[16];
    const float* b2   = (const float*)d_in[17];
    const float* Wmu  = (const float*)d_in[18];
    const float* bmu  = (const float*)d_in[19];
    const float* logv = (const float*)d_in[20];
    float* out = (float*)d_out;

    cudaFuncSetAttribute(k_sgemm, cudaFuncAttributeMaxDynamicSharedMemorySize, SG_SMEM);

    long zcur = OFF_Z0, zoth = OFF_Z1;

    k_wconv<<<64, 256>>>(W_no, NOISE_, 128);
    k_proj<<<(int)(((long)MTOT * C_ + 255) / 256), 256>>>(inputs, W_in, b_in, b_no, OFF_LX);
    k_zero_cnt<<<(B_ * N_ + 255) / 256, 256>>>();
    // x0 = noise@W_noise + (inputs@W_in + biases); z0 = elu(x0) + z-stats
    k_sgemm<<<GEMM_BLOCKS, 256, SG_SMEM>>>(noise, 0, NOISE_, -1L,
                                           -1L, OFF_LX, off_x(0), zcur, NOISE_, 128);
    k_hist<<<(B_ * E_ + 255) / 256, 256>>>(Lr);
    k_scan<<<B_, 1024>>>();
    k_scatter<<<(B_ * E_ + 255) / 256, 256>>>(Lr, Lc, Lv);

    int p = 0;
    for (int i = 0; i < NL_; ++i) {
        int cur = p, mid = (p + 1) % 3, nxt = (p + 2) % 3;
        // block j = 0
        k_lap<<<LAP_G, 256>>>(zcur);
        k_prep<<<1, 256>>>(rng + (long)(i * 2 + 0) * 256, rnb + (long)(i * 2 + 0) * 256,
                           rnW + (long)(i * 2 + 0) * 256 * 128, rnbs + (long)(i * 2 + 0) * 128, 256);
        k_sgemm<<<GEMM_BLOCKS, 256, SG_SMEM>>>((const float*)0, zcur, C_, OFF_LX,
                                               OFF_BP, -1L, off_x(mid), zoth, 2 * C_, 2 * C_);
        { long t = zcur; zcur = zoth; zoth = t; }
        // block j = 1 (+ residual from layer input)
        k_lap<<<LAP_G, 256>>>(zcur);
        k_prep<<<1, 256>>>(rng + (long)(i * 2 + 1) * 256, rnb + (long)(i * 2 + 1) * 256,
                           rnW + (long)(i * 2 + 1) * 256 * 128, rnbs + (long)(i * 2 + 1) * 128, 256);
        k_sgemm<<<GEMM_BLOCKS, 256, SG_SMEM>>>((const float*)0, zcur, C_, OFF_LX,
                                               OFF_BP, off_x(cur), off_x(nxt), zoth, 2 * C_, 2 * C_);
        { long t = zcur; zcur = zoth; zoth = t; }
        p = nxt;
    }

    // final head: h = z@fold(W2) + b2' ; out = elu(h)@W_mu + b_mu + inputs ; y = logvar
    k_prep<<<1, 256>>>(g2, be2, W2, b2, 128);
    int hb = (p + 1) % 3;
    k_sgemm<<<GEMM_BLOCKS, 256, SG_SMEM>>>((const float*)0, zcur, C_, -1L,
                                           OFF_BP, -1L, off_x(hb), -1L, C_, C_);
    k_final<<<MTOT / 8, 256>>>(off_x(hb), inputs, Wmu, bmu, logv, out);
}

// round 9
// speedup vs baseline: 1.4042x; 1.4042x over previous
#include <cuda_runtime.h>
#include <cstdint>

#define B_ 4
#define N_ 50000
#define E_ 800000
#define C_ 128
#define NOISE_ 100
#define NL_ 5
#define MTOT 200000
#define LAP_G 512
#define GEMM_BLOCKS 1563  /* ceil(200000/128) */

// ---------------- device heap (no allocations allowed) ----------------
#define SZ 25600000L                       // B*N*C floats
#define OFF_LX (3L*SZ)
#define OFF_Z0 (4L*SZ)
#define OFF_Z1 (5L*SZ)
#define OFF_VALS (6L*SZ)                   // sorted vals, B*E
#define OFF_PARTA (OFF_VALS + (long)B_*E_)             // GEMM z-stats partials
#define OFF_PARTB (OFF_PARTA + (long)GEMM_BLOCKS*256)  // lap lx-stats partials
#define OFF_P2 (OFF_PARTB + (long)LAP_G*256)           // stage-2 partials 80x256
#define OFF_SS (OFF_P2 + 80L*256)                      // BN scale per k (256)
#define OFF_WP (OFF_SS + 256L)
#define OFF_BP (OFF_WP + 256L*C_)
#define HEAP_F (OFF_BP + 128L)

#define OFFI_CNT 0
#define OFFI_RP  (B_*N_)                   // B*(N+1)
#define OFFI_COLS (OFFI_RP + B_*(N_+1))
#define IHEAP (OFFI_COLS + B_*E_)

__device__ __align__(256) float g_heap[HEAP_F];
__device__ __align__(256) int   g_iheap[IHEAP];

// ---------------- helpers ----------------
__device__ __forceinline__ float eluf(float x) {
    return x > 0.f ? x : (__expf(x) - 1.f);
}
__device__ __forceinline__ uint32_t smem_u32(const void* p) {
    uint32_t a;
    asm("{ .reg .u64 t; cvta.to.shared.u64 t, %1; cvt.u32.u64 %0, t; }" : "=r"(a) : "l"(p));
    return a;
}
__device__ __forceinline__ unsigned long long pk2(float x) {
    unsigned long long r; unsigned int u = __float_as_uint(x);
    asm("mov.b64 %0, {%1, %1};" : "=l"(r) : "r"(u));
    return r;
}
__device__ __forceinline__ void fma2(unsigned long long& d, unsigned long long a, unsigned long long b) {
    asm("fma.rn.f32x2 %0, %1, %2, %0;" : "+l"(d) : "l"(a), "l"(b));
}
__device__ __forceinline__ void upk2(unsigned long long v, float& lo, float& hi) {
    unsigned int a, b;
    asm("mov.b64 {%0, %1}, %2;" : "=r"(a), "=r"(b) : "l"(v));
    lo = __uint_as_float(a); hi = __uint_as_float(b);
}
__device__ __forceinline__ void cpa16(uint32_t dst, const void* src, uint32_t bytes) {
    asm volatile("cp.async.cg.shared.global [%0], [%1], 16, %2;"
                 :: "r"(dst), "l"(src), "r"(bytes) : "memory");
}
__device__ __forceinline__ void cpa_commit() {
    asm volatile("cp.async.commit_group;" ::: "memory");
}
template <int N>
__device__ __forceinline__ void cpa_wait() {
    asm volatile("cp.async.wait_group %0;" :: "n"(N) : "memory");
}

// ---------------- CSR build ----------------
__global__ void k_zero_cnt() {
    int i = blockIdx.x * 256 + threadIdx.x;
    if (i < B_ * N_) g_iheap[OFFI_CNT + i] = 0;
}

__global__ void k_hist(const int* __restrict__ rows) {
    int i = blockIdx.x * 256 + threadIdx.x;
    if (i < B_ * E_) {
        int b = i / E_;
        atomicAdd(&g_iheap[OFFI_CNT + b * N_ + rows[i]], 1);
    }
}

__global__ void k_scan() {  // grid = B_, block = 1024
    int b = blockIdx.x;
    int* cnt = g_iheap + OFFI_CNT + b * N_;
    int* rp  = g_iheap + OFFI_RP  + b * (N_ + 1);
    __shared__ int s[1024];
    __shared__ int carry;
    if (threadIdx.x == 0) { carry = 0; rp[0] = 0; }
    __syncthreads();
    for (int base = 0; base < N_; base += 1024) {
        int i = base + threadIdx.x;
        int v = (i < N_) ? cnt[i] : 0;
        s[threadIdx.x] = v;
        __syncthreads();
        for (int off = 1; off < 1024; off <<= 1) {
            int t = (threadIdx.x >= off) ? s[threadIdx.x - off] : 0;
            __syncthreads();
            s[threadIdx.x] += t;
            __syncthreads();
        }
        if (i < N_) { rp[i + 1] = carry + s[threadIdx.x]; cnt[i] = 0; }
        __syncthreads();
        if (threadIdx.x == 1023) carry += s[1023];
        __syncthreads();
    }
}

__global__ void k_scatter(const int* __restrict__ rows, const int* __restrict__ colsIn,
                          const float* __restrict__ valsIn) {
    int i = blockIdx.x * 256 + threadIdx.x;
    if (i >= B_ * E_) return;
    int b = i / E_;
    int r = rows[i];
    int pos = g_iheap[OFFI_RP + b * (N_ + 1) + r] + atomicAdd(&g_iheap[OFFI_CNT + b * N_ + r], 1);
    g_iheap[OFFI_COLS + b * E_ + pos] = colsIn[i];
    g_heap[OFF_VALS + (long)b * E_ + pos] = valsIn[i];
}

// ---------------- input projection small term ----------------
__global__ void k_proj(const float* __restrict__ inp, const float* __restrict__ Win,
                       const float* __restrict__ bin, const float* __restrict__ bno, long ooff) {
    long i = (long)blockIdx.x * 256 + threadIdx.x;
    if (i >= (long)MTOT * C_) return;
    int c = (int)(i & 127);
    long r = i >> 7;
    const float* p = inp + r * 3;
    float v = bin[c] + bno[c] + p[0] * Win[c] + p[1] * Win[C_ + c] + p[2] * Win[2 * C_ + c];
    g_heap[ooff + i] = v;
}

// ---------------- Laplacian gather + fused lx-stats -------------------------
__global__ void __launch_bounds__(256) k_lap(long zoff) {
    const float* z = g_heap + zoff;
    float* lx = g_heap + OFF_LX;
    int wid = threadIdx.x >> 5;
    int lane = threadIdx.x & 31;
    int c4 = lane * 4;
    float ss0 = 0.f, ss1 = 0.f, ss2 = 0.f, ss3 = 0.f;
    float qq0 = 0.f, qq1 = 0.f, qq2 = 0.f, qq3 = 0.f;

    for (int row = blockIdx.x * 8 + wid; row < MTOT; row += LAP_G * 8) {
        int b = row / N_;
        int rr = row - b * N_;
        const int* rp = g_iheap + OFFI_RP + b * (N_ + 1);
        const int* cols = g_iheap + OFFI_COLS + b * E_;
        const float* vals = g_heap + OFF_VALS + (long)b * E_;
        int e0 = rp[rr], e1 = rp[rr + 1];
        const float* zb = z + (size_t)b * N_ * C_;
        float4 acc = make_float4(0.f, 0.f, 0.f, 0.f);
        for (int e = e0; e < e1; e += 32) {
            int idx = e + lane;
            int cc = 0; float vv = 0.f;
            if (idx < e1) { cc = cols[idx]; vv = vals[idx]; }
            int mE = min(32, e1 - e);
            int t = 0;
            for (; t + 4 <= mE; t += 4) {
                int ci0 = __shfl_sync(0xffffffffu, cc, t);
                int ci1 = __shfl_sync(0xffffffffu, cc, t + 1);
                int ci2 = __shfl_sync(0xffffffffu, cc, t + 2);
                int ci3 = __shfl_sync(0xffffffffu, cc, t + 3);
                float v0 = __shfl_sync(0xffffffffu, vv, t);
                float v1 = __shfl_sync(0xffffffffu, vv, t + 1);
                float v2 = __shfl_sync(0xffffffffu, vv, t + 2);
                float v3 = __shfl_sync(0xffffffffu, vv, t + 3);
                float4 x0 = *reinterpret_cast<const float4*>(&zb[(size_t)ci0 * C_ + c4]);
                float4 x1 = *reinterpret_cast<const float4*>(&zb[(size_t)ci1 * C_ + c4]);
                float4 x2 = *reinterpret_cast<const float4*>(&zb[(size_t)ci2 * C_ + c4]);
                float4 x3 = *reinterpret_cast<const float4*>(&zb[(size_t)ci3 * C_ + c4]);
                acc.x += v0 * x0.x; acc.y += v0 * x0.y; acc.z += v0 * x0.z; acc.w += v0 * x0.w;
                acc.x += v1 * x1.x; acc.y += v1 * x1.y; acc.z += v1 * x1.z; acc.w += v1 * x1.w;
                acc.x += v2 * x2.x; acc.y += v2 * x2.y; acc.z += v2 * x2.z; acc.w += v2 * x2.w;
                acc.x += v3 * x3.x; acc.y += v3 * x3.y; acc.z += v3 * x3.z; acc.w += v3 * x3.w;
            }
            for (; t < mE; ++t) {
                int c = __shfl_sync(0xffffffffu, cc, t);
                float v = __shfl_sync(0xffffffffu, vv, t);
                float4 xv = *reinterpret_cast<const float4*>(&zb[(size_t)c * C_ + c4]);
                acc.x += v * xv.x; acc.y += v * xv.y; acc.z += v * xv.z; acc.w += v * xv.w;
            }
        }
        *reinterpret_cast<float4*>(&lx[(size_t)row * C_ + c4]) = acc;
        ss0 += acc.x; ss1 += acc.y; ss2 += acc.z; ss3 += acc.w;
        qq0 += acc.x * acc.x; qq1 += acc.y * acc.y; qq2 += acc.z * acc.z; qq3 += acc.w * acc.w;
    }

    __shared__ float sm[8 * 256];
    float* row = sm + wid * 256;
    row[c4 + 0] = ss0; row[c4 + 1] = ss1; row[c4 + 2] = ss2; row[c4 + 3] = ss3;
    row[128 + c4 + 0] = qq0; row[128 + c4 + 1] = qq1; row[128 + c4 + 2] = qq2; row[128 + c4 + 3] = qq3;
    __syncthreads();
    float tot = 0.f;
#pragma unroll
    for (int r = 0; r < 8; ++r) tot += sm[r * 256 + threadIdx.x];
    g_heap[OFF_PARTB + (long)blockIdx.x * 256 + threadIdx.x] = tot;
}

// ---------------- stage-1 partial reduce: PARTA(1563)+PARTB(512) -> P2[80] ---
__global__ void k_red1() {
    int t = threadIdx.x;
    int b = blockIdx.x;
    float s = 0.f;
    if (b < 64) {
        for (int g = b; g < GEMM_BLOCKS; g += 64)
            s += g_heap[OFF_PARTA + (long)g * 256 + t];
    } else {
        for (int g = b - 64; g < LAP_G; g += 16)
            s += g_heap[OFF_PARTB + (long)g * 256 + t];
    }
    g_heap[OFF_P2 + (long)b * 256 + t] = s;
}

// ---------------- stage-2: finish stats, fold BN, bias fold ------------------
// k<128 stats from P2 rows 0..63 (GEMM z), k>=128 from rows 64..79 (lap lx).
__global__ void k_prep(const float* __restrict__ gamma, const float* __restrict__ beta,
                       const float* __restrict__ Wraw, const float* __restrict__ braw, int K) {
    __shared__ float tt[256];
    int k = threadIdx.x;
    if (k < K) {
        int c = k & 127;
        float s = 0.f, q = 0.f;
        if (k < 128) {
#pragma unroll
            for (int g = 0; g < 64; ++g) {
                s += g_heap[OFF_P2 + (long)g * 256 + c];
                q += g_heap[OFF_P2 + (long)g * 256 + 128 + c];
            }
        } else {
#pragma unroll
            for (int g = 64; g < 80; ++g) {
                s += g_heap[OFF_P2 + (long)g * 256 + c];
                q += g_heap[OFF_P2 + (long)g * 256 + 128 + c];
            }
        }
        float inv = 1.f / (float)MTOT;
        float mean = s * inv;
        float var = q * inv - mean * mean;
        float sc = gamma[k] * rsqrtf(var + 1e-5f);
        g_heap[OFF_SS + k] = sc;
        tt[k] = beta[k] - mean * sc;
    }
    __syncthreads();
    if (threadIdx.x < C_) {
        int c = threadIdx.x;
        float acc = braw[c];
        for (int kk = 0; kk < K; ++kk) acc += tt[kk] * Wraw[kk * C_ + c];
        g_heap[OFF_BP + c] = acc;
    }
}

// ---------------- parallel Wp = ss .* Wraw ----------------------------------
__global__ void k_wfill(const float* __restrict__ Wraw, int K) {
    int idx = blockIdx.x * 256 + threadIdx.x;
    if (idx < K * C_)
        g_heap[OFF_WP + idx] = g_heap[OFF_SS + (idx >> 7)] * Wraw[idx];
}

// ---------------- raw weight -> fp32 Wp, zero-padded to Kpad rows -------------
__global__ void k_wconv(const float* __restrict__ W, int K, int Kpad) {
    float* Wp = g_heap + OFF_WP;
    for (int idx = blockIdx.x * 256 + threadIdx.x; idx < Kpad * C_; idx += gridDim.x * 256) {
        int k = idx >> 7;
        Wp[idx] = (k < K) ? W[idx] : 0.f;
    }
}

// ---------------- f32x2 SGEMM, 3-stage cp.async, fused z=elu(out) + z-stats --
#define AS_STRIDE 36
#define WS_STRIDE 132
#define AS_BYTES (128 * AS_STRIDE * 4)   /* 18432 */
#define WS_BYTES (32 * WS_STRIDE * 4)    /* 16896 */
#define BUF_BYTES (AS_BYTES + WS_BYTES)  /* 35328 */
#define SG_SMEM (3 * BUF_BYTES)          /* 105984 */

__global__ void __launch_bounds__(256, 2) k_sgemm(
    const float* __restrict__ Aext, long a0off, int lda0, long a1off,
    long boff, long roff, long ooff, long zoff, int K, int Kpad)
{
    extern __shared__ float smf[];
    const float* A0 = Aext ? Aext : g_heap + a0off;
    const float* A1 = (a1off >= 0) ? g_heap + a1off : (const float*)0;
    const float* Wp = g_heap + OFF_WP;
    const float* bias  = (boff >= 0) ? g_heap + boff : (const float*)0;
    const float* resid = (roff >= 0) ? g_heap + roff : (const float*)0;
    float* out = g_heap + ooff;
    float* zout = (zoff >= 0) ? g_heap + zoff : (float*)0;

    int tid = threadIdx.x;
    int tx = tid & 15, ty = tid >> 4;
    int rowBase = blockIdx.x * 128;
    int c0 = tx * 8;
    int r0 = ty * 8;
    uint32_t sbase = smem_u32(smf);

    auto prefetch = [&](int c) {
        uint32_t asA = sbase + (c % 3) * BUF_BYTES;
        uint32_t wsA = asA + AS_BYTES;
        int kbase = c * 32;
        const float* src; int slda; int ksb;
        if (A1 && kbase >= C_) { src = A1; slda = C_; ksb = kbase - C_; }
        else { src = A0; slda = lda0; ksb = kbase; }
#pragma unroll
        for (int j = 0; j < 4; ++j) {
            int idx = tid + j * 256;          // [m 128][kq 8]
            int m = idx >> 3, kq = idx & 7;
            int grow = rowBase + m;
            int gk = kbase + kq * 4;
            int nb = K - gk; nb = nb < 0 ? 0 : (nb > 4 ? 4 : nb);
            uint32_t bytes = (grow < MTOT) ? (uint32_t)(nb * 4) : 0u;
            int growc = grow < MTOT ? grow : (MTOT - 1);
            const float* s = src + (long)growc * slda + (ksb + kq * 4);
            uint32_t dst = asA + (uint32_t)((m * AS_STRIDE + ((kq * 4) ^ (((m >> 3) & 1) << 2))) * 4);
            cpa16(dst, s, bytes);
        }
#pragma unroll
        for (int j = 0; j < 4; ++j) {
            int idx = tid + j * 256;          // [k 32][cq 32]
            int k = idx >> 5, cq = idx & 31;
            uint32_t dst = wsA + (uint32_t)((k * WS_STRIDE + cq * 4) * 4);
            cpa16(dst, Wp + (long)(kbase + k) * C_ + cq * 4, 16);
        }
        cpa_commit();
    };

    unsigned long long acc[8][4];
#pragma unroll
    for (int i = 0; i < 8; i++)
#pragma unroll
        for (int j = 0; j < 4; j++) acc[i][j] = 0ull;

    int nC = Kpad >> 5;
    prefetch(0);
    if (nC > 1) prefetch(1);
    int sw = (ty & 1) << 2;

    for (int c = 0; c < nC; ++c) {
        if (c + 2 < nC)      { prefetch(c + 2); cpa_wait<2>(); }
        else if (c + 1 < nC) { cpa_wait<1>(); }
        else                 { cpa_wait<0>(); }
        __syncthreads();
        const float* asf = smf + (c % 3) * (BUF_BYTES / 4);
        const float* wsf = asf + (AS_BYTES / 4);
#pragma unroll
        for (int k4 = 0; k4 < 8; ++k4) {
            int kcol = (k4 * 4) ^ sw;
            float4 a4[8];
#pragma unroll
            for (int i = 0; i < 8; ++i)
                a4[i] = *reinterpret_cast<const float4*>(&asf[(r0 + i) * AS_STRIDE + kcol]);
#pragma unroll
            for (int kk = 0; kk < 4; ++kk) {
                const ulonglong2* wp2 = reinterpret_cast<const ulonglong2*>(&wsf[(k4 * 4 + kk) * WS_STRIDE + c0]);
                ulonglong2 w0 = wp2[0], w1 = wp2[1];
#pragma unroll
                for (int i = 0; i < 8; ++i) {
                    float av = (kk == 0) ? a4[i].x : (kk == 1) ? a4[i].y : (kk == 2) ? a4[i].z : a4[i].w;
                    unsigned long long a2 = pk2(av);
                    fma2(acc[i][0], a2, w0.x);
                    fma2(acc[i][1], a2, w0.y);
                    fma2(acc[i][2], a2, w1.x);
                    fma2(acc[i][3], a2, w1.y);
                }
            }
        }
        __syncthreads();
    }

    float bv[8];
#pragma unroll
    for (int j = 0; j < 8; j++) bv[j] = bias ? bias[c0 + j] : 0.f;
    float st_s[8], st_q[8];
#pragma unroll
    for (int j = 0; j < 8; j++) { st_s[j] = 0.f; st_q[j] = 0.f; }

#pragma unroll
    for (int i = 0; i < 8; i++) {
        int grow = rowBase + r0 + i;
        if (grow >= MTOT) continue;
        float o[8];
#pragma unroll
        for (int j = 0; j < 4; j++) {
            float lo, hi;
            upk2(acc[i][j], lo, hi);
            o[2 * j] = lo + bv[2 * j];
            o[2 * j + 1] = hi + bv[2 * j + 1];
        }
        if (resid) {
#pragma unroll
            for (int j = 0; j < 8; j++) o[j] += resid[(long)grow * C_ + c0 + j];
        }
        float4* op = reinterpret_cast<float4*>(&out[(long)grow * C_ + c0]);
        op[0] = make_float4(o[0], o[1], o[2], o[3]);
        op[1] = make_float4(o[4], o[5], o[6], o[7]);
        if (zout) {
            float zv[8];
#pragma unroll
            for (int j = 0; j < 8; j++) {
                zv[j] = eluf(o[j]);
                st_s[j] += zv[j];
                st_q[j] += zv[j] * zv[j];
            }
            float4* zp = reinterpret_cast<float4*>(&zout[(long)grow * C_ + c0]);
            zp[0] = make_float4(zv[0], zv[1], zv[2], zv[3]);
            zp[1] = make_float4(zv[4], zv[5], zv[6], zv[7]);
        }
    }

    if (zout) {   // per-CTA stats partial (deterministic)
        __syncthreads();
#pragma unroll
        for (int j = 0; j < 8; j++) {
            smf[ty * 256 + c0 + j] = st_s[j];
            smf[ty * 256 + 128 + c0 + j] = st_q[j];
        }
        __syncthreads();
        float tot = 0.f;
#pragma unroll
        for (int r = 0; r < 16; ++r) tot += smf[r * 256 + tid];
        g_heap[OFF_PARTA + (long)blockIdx.x * 256 + tid] = tot;
    }
}

// ---------------- final: mu = elu(h)@W_mu + b_mu + inputs; y = logvar --------
__global__ void k_final(long hoff, const float* __restrict__ inp,
                        const float* __restrict__ Wmu, const float* __restrict__ bmu,
                        const float* __restrict__ logv, float* __restrict__ out) {
    int warp = (blockIdx.x * blockDim.x + threadIdx.x) >> 5;
    int lane = threadIdx.x & 31;
    if (warp >= MTOT) return;
    const float* h = g_heap + hoff + (size_t)warp * C_;
    float4 hv = *reinterpret_cast<const float4*>(&h[lane * 4]);
    float e0 = eluf(hv.x), e1 = eluf(hv.y), e2 = eluf(hv.z), e3 = eluf(hv.w);
    int c0 = lane * 4;
    float p0, p1, p2;
    p0 = e0 * Wmu[c0 * 3 + 0] + e1 * Wmu[(c0 + 1) * 3 + 0] + e2 * Wmu[(c0 + 2) * 3 + 0] + e3 * Wmu[(c0 + 3) * 3 + 0];
    p1 = e0 * Wmu[c0 * 3 + 1] + e1 * Wmu[(c0 + 1) * 3 + 1] + e2 * Wmu[(c0 + 2) * 3 + 1] + e3 * Wmu[(c0 + 3) * 3 + 1];
    p2 = e0 * Wmu[c0 * 3 + 2] + e1 * Wmu[(c0 + 1) * 3 + 2] + e2 * Wmu[(c0 + 2) * 3 + 2] + e3 * Wmu[(c0 + 3) * 3 + 2];
#pragma unroll
    for (int off = 16; off; off >>= 1) {
        p0 += __shfl_xor_sync(0xffffffffu, p0, off);
        p1 += __shfl_xor_sync(0xffffffffu, p1, off);
        p2 += __shfl_xor_sync(0xffffffffu, p2, off);
    }
    if (lane < 3) {
        float pv = (lane == 0) ? p0 : ((lane == 1) ? p1 : p2);
        float mu = pv + bmu[lane] + inp[(size_t)warp * 3 + lane];
        out[(size_t)warp * 3 + lane] = mu;
        out[(size_t)MTOT * 3 + (size_t)warp * 3 + lane] = logv[0];
    }
}

// ---------------- host orchestration ----------------
static long off_x(int i) { return (long)i * SZ; }

extern "C" void kernel_launch(void* const* d_in, const int* in_sizes, int n_in,
                              void* d_out, int out_size) {
    const float* inputs = (const float*)d_in[0];
    const float* noise  = (const float*)d_in[1];
    const int*   Lr = (const int*)d_in[3];
    const int*   Lc = (const int*)d_in[4];
    const float* Lv = (const float*)d_in[5];
    const float* W_in = (const float*)d_in[6];
    const float* b_in = (const float*)d_in[7];
    const float* W_no = (const float*)d_in[8];
    const float* b_no = (const float*)d_in[9];
    const float* rng  = (const float*)d_in[10];
    const float* rnb  = (const float*)d_in[11];
    const float* rnW  = (const float*)d_in[12];
    const float* rnbs = (const float*)d_in[13];
    const float* g2   = (const float*)d_in[14];
    const float* be2  = (const float*)d_in[15];
    const float* W2   = (const float*)d_in[16];
    const float* b2   = (const float*)d_in[17];
    const float* Wmu  = (const float*)d_in[18];
    const float* bmu  = (const float*)d_in[19];
    const float* logv = (const float*)d_in[20];
    float* out = (float*)d_out;

    cudaFuncSetAttribute(k_sgemm, cudaFuncAttributeMaxDynamicSharedMemorySize, SG_SMEM);

    long zcur = OFF_Z0, zoth = OFF_Z1;

    k_wconv<<<64, 256>>>(W_no, NOISE_, 128);
    k_proj<<<(int)(((long)MTOT * C_ + 255) / 256), 256>>>(inputs, W_in, b_in, b_no, OFF_LX);
    k_zero_cnt<<<(B_ * N_ + 255) / 256, 256>>>();
    // x0 = noise@W_noise + (inputs@W_in + biases); z0 = elu(x0) + z-stats
    k_sgemm<<<GEMM_BLOCKS, 256, SG_SMEM>>>(noise, 0, NOISE_, -1L,
                                           -1L, OFF_LX, off_x(0), zcur, NOISE_, 128);
    k_hist<<<(B_ * E_ + 255) / 256, 256>>>(Lr);
    k_scan<<<B_, 1024>>>();
    k_scatter<<<(B_ * E_ + 255) / 256, 256>>>(Lr, Lc, Lv);

    int p = 0;
    for (int i = 0; i < NL_; ++i) {
        int cur = p, mid = (p + 1) % 3, nxt = (p + 2) % 3;
        for (int j = 0; j < 2; ++j) {
            const float* ga = rng + (long)(i * 2 + j) * 256;
            const float* be = rnb + (long)(i * 2 + j) * 256;
            const float* Wr = rnW + (long)(i * 2 + j) * 256 * 128;
            const float* br = rnbs + (long)(i * 2 + j) * 128;
            k_lap<<<LAP_G, 256>>>(zcur);
            k_red1<<<80, 256>>>();
            k_prep<<<1, 256>>>(ga, be, Wr, br, 256);
            k_wfill<<<128, 256>>>(Wr, 256);
            long rsd = (j == 0) ? -1L : off_x(cur);
            long dst = (j == 0) ? off_x(mid) : off_x(nxt);
            k_sgemm<<<GEMM_BLOCKS, 256, SG_SMEM>>>((const float*)0, zcur, C_, OFF_LX,
                                                   OFF_BP, rsd, dst, zoth, 2 * C_, 2 * C_);
            { long t = zcur; zcur = zoth; zoth = t; }
        }
        p = nxt;
    }

    // final head: h = z@fold(W2) + b2' ; out = elu(h)@W_mu + b_mu + inputs
    k_red1<<<80, 256>>>();
    k_prep<<<1, 256>>>(g2, be2, W2, b2, 128);
    k_wfill<<<64, 256>>>(W2, 128);
    int hb = (p + 1) % 3;
    k_sgemm<<<GEMM_BLOCKS, 256, SG_SMEM>>>((const float*)0, zcur, C_, -1L,
                                           OFF_BP, -1L, off_x(hb), -1L, C_, C_);
    k_final<<<MTOT / 8, 256>>>(off_x(hb), inputs, Wmu, bmu, logv, out);
}